// round 15
// baseline (speedup 1.0000x reference)
#include <cuda_runtime.h>
#include <cuda_bf16.h>
#include <math.h>

#define L     8
#define NH    16
#define DH    64
#define SMAX  2048
#define H     1024
#define FFN   4096
#define ENC   1500
#define VOCAB 8192
#define FCH   48
#define CH    64    // attention key chunks
#define CSH   8.0f  // constant softmax shift (softmax is shift-invariant)

// ---------------- device state ----------------
__device__ __align__(16) float g_x[H];
__device__ __align__(16) float g_qkv[3 * H];
__device__ __align__(16) float g_qc[H];
__device__ __align__(16) float g_U[NH * H];
__device__ __align__(16) float g_sc[NH * ENC];
__device__ __align__(16) float g_W[NH * H];
__device__ __align__(16) float g_outc[H];
__device__ __align__(16) float g_ffn[FFN];
__device__ __align__(16) float g_logits[VOCAB];
__device__ float g_pm[NH * CH];
__device__ float g_ps[NH * CH];
__device__ __align__(16) float g_po[NH * CH * DH];
__device__ float g_ssum[NH];
__device__ int   g_step_fallback[1] = {512};

// ---------------- PDL helpers ----------------
__device__ __forceinline__ void pdl_trigger() {
#if defined(__CUDA_ARCH__) && __CUDA_ARCH__ >= 900
    cudaTriggerProgrammaticLaunchCompletion();
#endif
}
__device__ __forceinline__ void pdl_sync() {
#if defined(__CUDA_ARCH__) && __CUDA_ARCH__ >= 900
    cudaGridDependencySynchronize();
#endif
}

// ---------------- block reductions ----------------
__device__ __forceinline__ float br_sum(float v, float* sb) {
    int tid = threadIdx.x, lane = tid & 31, w = tid >> 5;
#pragma unroll
    for (int o = 16; o; o >>= 1) v += __shfl_down_sync(0xffffffffu, v, o);
    if (lane == 0) sb[w] = v;
    __syncthreads();
    if (tid < 32) {
        int nw = (blockDim.x + 31) >> 5;
        float x = (tid < nw) ? sb[tid] : 0.0f;
#pragma unroll
        for (int o = 16; o; o >>= 1) x += __shfl_down_sync(0xffffffffu, x, o);
        if (tid == 0) sb[0] = x;
    }
    __syncthreads();
    float r = sb[0];
    __syncthreads();
    return r;
}

__device__ __forceinline__ float br_max(float v, float* sb) {
    int tid = threadIdx.x, lane = tid & 31, w = tid >> 5;
#pragma unroll
    for (int o = 16; o; o >>= 1) v = fmaxf(v, __shfl_down_sync(0xffffffffu, v, o));
    if (lane == 0) sb[w] = v;
    __syncthreads();
    if (tid < 32) {
        int nw = (blockDim.x + 31) >> 5;
        float x = (tid < nw) ? sb[tid] : -1e30f;
#pragma unroll
        for (int o = 16; o; o >>= 1) x = fmaxf(x, __shfl_down_sync(0xffffffffu, x, o));
        if (tid == 0) sb[0] = x;
    }
    __syncthreads();
    float r = sb[0];
    __syncthreads();
    return r;
}

__device__ __forceinline__ void ln_stats(float* sb, float& mean, float& rstd) {
    int tid = threadIdx.x;
    float s = 0.f;
    for (int i = tid; i < H; i += blockDim.x) s += g_x[i];
    mean = br_sum(s, sb) * (1.0f / H);
    float v = 0.f;
    for (int i = tid; i < H; i += blockDim.x) { float d = g_x[i] - mean; v += d * d; }
    rstd = rsqrtf(br_sum(v, sb) * (1.0f / H) + 1e-5f);
}

// ---------------- kernels ----------------

// cache copy: 148 blocks x 512 threads => 1 block/SM, 25% thread occupancy.
// Leaves 1536 thr/SM free so the PDL chain schedules UNDER the copy.
__global__ void k_copy_p(const float4* __restrict__ ck, const float4* __restrict__ cv,
                         float4* __restrict__ nk, float4* __restrict__ nv,
                         const int* __restrict__ stepp) {
    pdl_trigger();
    int step = stepp[0];
    const size_t half = (size_t)L * NH * SMAX * 16;
    const size_t total = 2 * half;
    size_t stride = (size_t)gridDim.x * blockDim.x;
    for (size_t idx = (size_t)blockIdx.x * blockDim.x + threadIdx.x; idx < total; idx += stride) {
        const float4* src; float4* dst; size_t pos;
        if (idx < half) { src = ck; dst = nk; pos = idx; }
        else            { src = cv; dst = nv; pos = idx - half; }
        int t = (int)((pos >> 4) & (SMAX - 1));
        if (t < step)      dst[pos] = src[pos];
        else if (t > step) dst[pos] = make_float4(0.f, 0.f, 0.f, 0.f);
    }
}

// x = tok+pos; zero qkv + logits
__global__ void k_init(const int* __restrict__ idp, const int* __restrict__ stepp,
                       const float* __restrict__ tok, const float* __restrict__ pos) {
    pdl_trigger();
    int tid = threadIdx.x;  // 1024
    int id = idp[0], st = stepp[0];
    g_x[tid] = tok[(size_t)id * H + tid] + pos[(size_t)st * H + tid];
    for (int i = tid; i < 3 * H; i += 1024) g_qkv[i] = 0.f;
    for (int i = tid; i < VOCAB; i += 1024) g_logits[i] = 0.f;
}

// qkv += LN1(x) @ [Wq|Wk|Wv] (grid (12,32), 256); scalar prefetch R=32 [R12]
__global__ void k_gemv3_ln(const float* __restrict__ Wq, const float* __restrict__ Wk,
                           const float* __restrict__ Wv,
                           const float* __restrict__ g, const float* __restrict__ b) {
    __shared__ float sb[32];
    __shared__ float hc[32];
    int tid = threadIdx.x;
    pdl_trigger();
    int i0 = blockIdx.y * 32;
    int j = blockIdx.x * 256 + tid;  // 0..3071
    const float* Wm = (j < H) ? Wq : ((j < 2 * H) ? Wk : Wv);
    int jj = j & (H - 1);
    float w[32];
#pragma unroll
    for (int r = 0; r < 32; r++) w[r] = Wm[(size_t)(i0 + r) * H + jj];
    pdl_sync();
    float mean, rstd;
    ln_stats(sb, mean, rstd);
    if (tid < 32) { int i = i0 + tid; hc[tid] = (g_x[i] - mean) * rstd * g[i] + b[i]; }
    __syncthreads();
    float acc = 0.f;
#pragma unroll
    for (int r = 0; r < 32; r++) acc += hc[r] * w[r];
    atomicAdd(&g_qkv[j], acc);
}

// out += LN(x; g,b) @ W  (grid: n_out/256 x K/32, block 256); scalar prefetch R=32 [R12]
__global__ void k_gemv_ln(const float* __restrict__ Wm,
                          const float* __restrict__ g, const float* __restrict__ b,
                          float* __restrict__ out, int n_out) {
    __shared__ float sb[32];
    __shared__ float hc[32];
    int tid = threadIdx.x;
    pdl_trigger();
    int i0 = blockIdx.y * 32;
    int j = blockIdx.x * 256 + tid;
    float w[32];
#pragma unroll
    for (int r = 0; r < 32; r++) w[r] = Wm[(size_t)(i0 + r) * n_out + j];
    pdl_sync();
    float mean, rstd;
    ln_stats(sb, mean, rstd);
    if (tid < 32) { int i = i0 + tid; hc[tid] = (g_x[i] - mean) * rstd * g[i] + b[i]; }
    __syncthreads();
    float acc = 0.f;
#pragma unroll
    for (int r = 0; r < 32; r++) acc += hc[r] * w[r];
    atomicAdd(&out[j], acc);
}

// out += (relu?)a @ W; SER serial 32-row chunks per block; optional zero buffer [R12]
template <int SER>
__global__ void k_gemv_plain(const float* __restrict__ Wm, const float* __restrict__ a,
                             float* __restrict__ out, int n_out, int relu,
                             float* z1, int zn1) {
    __shared__ float ac[32 * SER];
    int tid = threadIdx.x;
    pdl_trigger();
    int i0 = blockIdx.y * 32 * SER;
    int j = blockIdx.x * 256 + tid;
    float w[32];
#pragma unroll
    for (int r = 0; r < 32; r++) w[r] = Wm[(size_t)(i0 + r) * n_out + j];
    pdl_sync();
    if (zn1 > 0) {
        int gt = (blockIdx.y * gridDim.x + blockIdx.x) * 256 + tid;
        int T = gridDim.x * gridDim.y * 256;
        for (int k = gt; k < zn1; k += T) z1[k] = 0.f;
    }
    if (tid < 32 * SER) { float x = a[i0 + tid]; if (relu) x = fmaxf(x, 0.f); ac[tid] = x; }
    __syncthreads();
    float acc = 0.f;
#pragma unroll
    for (int s = 0; s < SER; s++) {
#pragma unroll
        for (int r = 0; r < 32; r++) acc += ac[s * 32 + r] * w[r];
        if (s + 1 < SER) {
#pragma unroll
            for (int r = 0; r < 32; r++)
                w[r] = Wm[(size_t)(i0 + (s + 1) * 32 + r) * n_out + j];
        }
    }
    atomicAdd(&out[j], acc);
}

// x += merge(attn partials) @ Wo (grid (4,32), 256); zeros g_qc + g_ssum [R14]
__global__ void k_gemv_merge(const float* __restrict__ Wm) {
    __shared__ float ac[32];
    int tid = threadIdx.x;
    pdl_trigger();
    int i0 = blockIdx.y * 32;
    int j = blockIdx.x * 256 + tid;
    float w[32];
#pragma unroll
    for (int r = 0; r < 32; r++) w[r] = Wm[(size_t)(i0 + r) * H + j];
    pdl_sync();
    int gt = (blockIdx.y * gridDim.x + blockIdx.x) * 256 + tid;
    int T = gridDim.x * gridDim.y * 256;
    for (int k = gt; k < H; k += T) g_qc[k] = 0.f;
    for (int k = gt; k < NH; k += T) g_ssum[k] = 0.f;
    if (tid < 32) {
        int i = i0 + tid;
        int h = i >> 6, d = i & 63;
        float M = -1e30f;
#pragma unroll
        for (int c = 0; c < CH; c++) M = fmaxf(M, g_pm[h * CH + c]);
        float S = 0.f, o = 0.f;
#pragma unroll
        for (int c = 0; c < CH; c++) {
            float e = __expf(g_pm[h * CH + c] - M);
            S += g_ps[h * CH + c] * e;
            o += e * g_po[(h * CH + c) * 64 + d];
        }
        ac[tid] = o / S;
    }
    __syncthreads();
    float acc = 0.f;
#pragma unroll
    for (int r = 0; r < 32; r++) acc += ac[r] * w[r];
    atomicAdd(&g_x[j], acc);
}

// flash-decode partials (grid (16,CH), block 128) [R12]
__global__ void k_attn_part(const float* __restrict__ ck, const float* __restrict__ cv,
                            float* __restrict__ nk, float* __restrict__ nv,
                            const int* __restrict__ stepp, int l) {
    __shared__ float2 q2[32];
    __shared__ float sc[72];
    __shared__ float sb[32];
    __shared__ float2 red2[128];
    int tid = threadIdx.x;
    pdl_trigger();
    pdl_sync();
    int h = blockIdx.x, c = blockIdx.y;
    int step = stepp[0];
    int n = step + 1;
    int cs = (n + CH - 1) / CH;
    int k0 = c * cs;
    int k1 = min(n, k0 + cs);
    int cnt = k1 - k0;
    int w = tid >> 5, lane = tid & 31;
    if (tid < 32) q2[tid] = ((const float2*)&g_qkv[h * 64])[tid];
    __syncthreads();
    float2 q = q2[lane];
    const float* kbase = ck + (size_t)(l * NH + h) * SMAX * DH;
    for (int kk = k0 + w; kk < k1; kk += 4) {
        const float2* kp = (kk < step) ? (const float2*)(kbase + (size_t)kk * DH)
                                       : (const float2*)(&g_qkv[H + h * 64]);
        float2 kv = kp[lane];
        float v = kv.x * q.x + kv.y * q.y;
#pragma unroll
        for (int o = 16; o; o >>= 1) v += __shfl_down_sync(0xffffffffu, v, o);
        if (lane == 0) sc[kk - k0] = v * 0.125f;
    }
    __syncthreads();
    float m = -1e30f;
    for (int i = tid; i < cnt; i += 128) m = fmaxf(m, sc[i]);
    m = br_max(m, sb);
    float s = 0.f;
    for (int i = tid; i < cnt; i += 128) { float e = __expf(sc[i] - m); sc[i] = e; s += e; }
    s = br_sum(s, sb);
    const float* vbase = cv + (size_t)(l * NH + h) * SMAX * DH;
    float2 acc = make_float2(0.f, 0.f);
    for (int kk = k0 + w; kk < k1; kk += 4) {
        const float2* vp = (kk < step) ? (const float2*)(vbase + (size_t)kk * DH)
                                       : (const float2*)(&g_qkv[2 * H + h * 64]);
        float wgt = sc[kk - k0];
        float2 v = vp[lane];
        acc.x += wgt * v.x; acc.y += wgt * v.y;
    }
    red2[tid] = acc;
    __syncthreads();
    if (w == 0) {
        float2 o;
        o.x = red2[lane].x + red2[32 + lane].x + red2[64 + lane].x + red2[96 + lane].x;
        o.y = red2[lane].y + red2[32 + lane].y + red2[64 + lane].y + red2[96 + lane].y;
        g_po[(h * CH + c) * 64 + 2 * lane]     = o.x;
        g_po[(h * CH + c) * 64 + 2 * lane + 1] = o.y;
        if (lane == 0) { g_pm[h * CH + c] = m; g_ps[h * CH + c] = s; }
    }
    if (c == 0 && tid >= 64) {
        int t2 = tid - 64;
        size_t base = ((size_t)(l * NH + h) * SMAX + step) * DH;
        if (t2 < 32) ((float2*)(nk + base))[t2]      = ((const float2*)(g_qkv + H + h * 64))[t2];
        else         ((float2*)(nv + base))[t2 - 32] = ((const float2*)(g_qkv + 2 * H + h * 64))[t2 - 32];
    }
}

// U[h][i]; zeros g_W and g_outc. grid 128, block 256 [R14]
__global__ void k_U(const float* __restrict__ Ck) {
    __shared__ float4 qs[256];
    int tid = threadIdx.x;
    pdl_trigger();
    pdl_sync();
    qs[tid] = ((const float4*)g_qc)[tid];
    int gt = blockIdx.x * 256 + tid;  // 0..32767
    if (gt < NH * H) g_W[gt] = 0.f;
    else if (gt < NH * H + H) g_outc[gt - NH * H] = 0.f;
    __syncthreads();
    float4 q = qs[tid];
    int i0 = blockIdx.x * 8;
    int h = tid >> 4;
#pragma unroll
    for (int r = 0; r < 8; r++) {
        int i = i0 + r;
        float4 w = ((const float4*)(Ck + (size_t)i * H))[tid];
        float v = w.x * q.x + w.y * q.y + w.z * q.z + w.w * q.w;
        v += __shfl_down_sync(0xffffffffu, v, 8);
        v += __shfl_down_sync(0xffffffffu, v, 4);
        v += __shfl_down_sync(0xffffffffu, v, 2);
        v += __shfl_down_sync(0xffffffffu, v, 1);
        if ((tid & 15) == 0) g_U[h * H + i] = v;
    }
}

// scores -> exp(s - CSH) written directly; per-head sums via one atomic per warp [R14]
__global__ void k_scores(const float* __restrict__ enc, const float* __restrict__ cmask) {
    pdl_trigger();
    pdl_sync();
    int w = threadIdx.x >> 5, lane = threadIdx.x & 31;
    const float4* up = (const float4*)(g_U + w * H);
    float4 u[8];
#pragma unroll
    for (int j = 0; j < 8; j++) u[j] = up[lane + 32 * j];
    float psum = 0.f;
#pragma unroll
    for (int ff = 0; ff < 8; ff++) {
        int f = blockIdx.x * 8 + ff;
        if (f >= ENC) break;
        const float4* ep = (const float4*)(enc + (size_t)f * H);
        float acc = 0.f;
#pragma unroll
        for (int j = 0; j < 8; j++) {
            float4 e = ep[lane + 32 * j];
            acc += e.x * u[j].x + e.y * u[j].y + e.z * u[j].z + e.w * u[j].w;
        }
#pragma unroll
        for (int o = 16; o; o >>= 1) acc += __shfl_down_sync(0xffffffffu, acc, o);
        if (lane == 0) {
            float e = __expf(acc * 0.125f + cmask[f] - CSH);
            g_sc[w * ENC + f] = e;
            psum += e;
        }
    }
    if (lane == 0) atomicAdd(&g_ssum[w], psum);
}

// W[h][cols] += (exp-scores / ssum[h]) @ enc. grid (4,32), block 256 [R14]
__global__ void k_wsum(const float* __restrict__ enc) {
    __shared__ float at[4 * FCH];
    __shared__ float rs[4];
    int tid = threadIdx.x, fc = blockIdx.y, hg = blockIdx.x;
    pdl_trigger();
    pdl_sync();
    if (tid < 4) rs[tid] = 1.0f / g_ssum[hg * 4 + tid];
    __syncthreads();
    for (int idx = tid; idx < 4 * FCH; idx += 256) {
        int hh = idx / FCH, k = idx % FCH;
        int f = fc * FCH + k;
        at[idx] = (f < ENC) ? g_sc[(hg * 4 + hh) * ENC + f] * rs[hh] : 0.f;
    }
    __syncthreads();
    int c0 = tid * 4;
    float4 acc[4];
#pragma unroll
    for (int hh = 0; hh < 4; hh++) acc[hh] = make_float4(0.f, 0.f, 0.f, 0.f);
    int fend = min(FCH, ENC - fc * FCH);
    for (int k = 0; k < fend; k++) {
        float4 e = *(const float4*)(enc + (size_t)(fc * FCH + k) * H + c0);
#pragma unroll
        for (int hh = 0; hh < 4; hh++) {
            float a = at[hh * FCH + k];
            acc[hh].x += a * e.x; acc[hh].y += a * e.y;
            acc[hh].z += a * e.z; acc[hh].w += a * e.w;
        }
    }
#pragma unroll
    for (int hh = 0; hh < 4; hh++) {
        float* o = &g_W[(hg * 4 + hh) * H + c0];
        atomicAdd(o, acc[hh].x); atomicAdd(o + 1, acc[hh].y);
        atomicAdd(o + 2, acc[hh].z); atomicAdd(o + 3, acc[hh].w);
    }
}

// outc[col] += sum_i W[h(col),i]*Cv[i,col]; zero g_ffn. grid 128, block 256 [R12]
__global__ void k_outc(const float* __restrict__ Cv) {
    int tid = threadIdx.x;
    pdl_trigger();
    pdl_sync();
    int c0 = tid * 4;
    int h = tid >> 4;
    int i0 = blockIdx.x * 8;
    float4 acc = make_float4(0.f, 0.f, 0.f, 0.f);
#pragma unroll
    for (int r = 0; r < 8; r++) {
        int i = i0 + r;
        float wv = g_W[h * H + i];
        float4 cv4 = *(const float4*)(Cv + (size_t)i * H + c0);
        acc.x += wv * cv4.x; acc.y += wv * cv4.y;
        acc.z += wv * cv4.z; acc.w += wv * cv4.w;
    }
    float* o = &g_outc[c0];
    atomicAdd(o, acc.x); atomicAdd(o + 1, acc.y);
    atomicAdd(o + 2, acc.z); atomicAdd(o + 3, acc.w);
    int gt = blockIdx.x * 256 + tid;
    if (gt < FFN) g_ffn[gt] = 0.f;
}

__global__ void k_logsoftmax(float* __restrict__ out) {
    __shared__ float sb[32];
    int tid = threadIdx.x;
    pdl_trigger();
    pdl_sync();
    float m = -1e30f;
    for (int i = tid; i < VOCAB; i += 256) m = fmaxf(m, g_logits[i]);
    m = br_max(m, sb);
    float s = 0.f;
    for (int i = tid; i < VOCAB; i += 256) s += __expf(g_logits[i] - m);
    s = br_sum(s, sb);
    float ls = logf(s);
    for (int i = tid; i < VOCAB; i += 256) out[i] = g_logits[i] - m - ls;
}

// ---------------- host ----------------
template <typename... Args>
static inline void lp(void (*k)(Args...), dim3 g, dim3 b, Args... a) {
    cudaLaunchConfig_t cfg = {};
    cfg.gridDim = g; cfg.blockDim = b;
    cfg.dynamicSmemBytes = 0; cfg.stream = 0;
    cudaLaunchAttribute at[1];
    at[0].id = cudaLaunchAttributeProgrammaticStreamSerialization;
    at[0].val.programmaticStreamSerializationAllowed = 1;
    cfg.attrs = at; cfg.numAttrs = 1;
    cudaLaunchKernelEx(&cfg, k, a...);
}

extern "C" void kernel_launch(void* const* d_in, const int* in_sizes, int n_in,
                              void* d_out, int out_size) {
    int has_step = (n_in >= 27) ? 1 : 0;
    int idx = 0;
    const int*   input_id = (const int*)d_in[idx++];
    const float* enc      = (const float*)d_in[idx++];
    const float* ck       = (const float*)d_in[idx++];
    const float* cv       = (const float*)d_in[idx++];
    const int*   stepp    = nullptr;
    if (has_step) stepp = (const int*)d_in[idx++];
    const float* cmask = (const float*)d_in[idx++];
    const float* tok   = (const float*)d_in[idx++];
    const float* pos   = (const float*)d_in[idx++];
    const float* Wq = (const float*)d_in[idx++];
    const float* Wk = (const float*)d_in[idx++];
    const float* Wv = (const float*)d_in[idx++];
    const float* Wo = (const float*)d_in[idx++];
    const float* Cq = (const float*)d_in[idx++];
    const float* Ck = (const float*)d_in[idx++];
    const float* Cv = (const float*)d_in[idx++];
    const float* Co = (const float*)d_in[idx++];
    const float* W1 = (const float*)d_in[idx++];
    const float* W2 = (const float*)d_in[idx++];
    const float* ln1g = (const float*)d_in[idx++];
    const float* ln1b = (const float*)d_in[idx++];
    const float* ln2g = (const float*)d_in[idx++];
    const float* ln2b = (const float*)d_in[idx++];
    const float* ln3g = (const float*)d_in[idx++];
    const float* ln3b = (const float*)d_in[idx++];
    const float* lnfg = (const float*)d_in[idx++];
    const float* lnfb = (const float*)d_in[idx++];
    const float* Wout = (const float*)d_in[idx++];

    if (!stepp) {
        void* p;
        cudaGetSymbolAddress(&p, g_step_fallback);
        stepp = (const int*)p;
    }

    float* out = (float*)d_out;
    float* nk = out + VOCAB;
    float* nv = nk + (size_t)L * NH * SMAX * DH;

    float *p_qc, *p_outc, *p_ffn, *p_logits, *p_qkv, *p_x;
    cudaGetSymbolAddress((void**)&p_x, g_x);
    cudaGetSymbolAddress((void**)&p_qc, g_qc);
    cudaGetSymbolAddress((void**)&p_outc, g_outc);
    cudaGetSymbolAddress((void**)&p_ffn, g_ffn);
    cudaGetSymbolAddress((void**)&p_logits, g_logits);
    cudaGetSymbolAddress((void**)&p_qkv, g_qkv);

    // cache copy: 148x512 => 25% of each SM; chain pipelines under it
    lp(k_copy_p, dim3(148), dim3(512),
       (const float4*)ck, (const float4*)cv, (float4*)nk, (float4*)nv, stepp);
    lp(k_init, dim3(1), dim3(1024), input_id, stepp, tok, pos);

    for (int l = 0; l < L; l++) {
        size_t o = (size_t)l * H * H;
        size_t o1 = (size_t)l * H * FFN;
        size_t o2 = (size_t)l * FFN * H;
        // self-attention
        lp(k_gemv3_ln, dim3(12, 32), dim3(256), Wq + o, Wk + o, Wv + o,
           (const float*)(ln1g + l * H), (const float*)(ln1b + l * H));
        lp(k_attn_part, dim3(16, CH), dim3(128), ck, cv, nk, nv, stepp, l);
        lp(k_gemv_merge, dim3(4, 32), dim3(256), Wo + o);
        // cross-attention (softmax node eliminated: shift-invariant exp + atomic row sums)
        lp(k_gemv_ln, dim3(4, 32), dim3(256), Cq + o,
           (const float*)(ln2g + l * H), (const float*)(ln2b + l * H), p_qc, H);
        lp(k_U, dim3(128), dim3(256), Ck + o);
        lp(k_scores, dim3(188), dim3(512), enc, cmask);
        lp(k_wsum, dim3(4, 32), dim3(256), enc);
        lp(k_outc, dim3(128), dim3(256), Cv + o);
        lp(k_gemv_plain<1>, dim3(4, 32), dim3(256), Co + o, (const float*)p_outc, p_x, H, 0,
           (float*)nullptr, 0);
        // FFN
        lp(k_gemv_ln, dim3(16, 32), dim3(256), W1 + o1,
           (const float*)(ln3g + l * H), (const float*)(ln3b + l * H), p_ffn, FFN);
        lp(k_gemv_plain<2>, dim3(4, 64), dim3(256), W2 + o2, (const float*)p_ffn, p_x, H, 1,
           p_qkv, 3 * H);
    }
    // final projection + log-softmax
    lp(k_gemv_ln, dim3(32, 32), dim3(256), Wout, lnfg, lnfb, p_logits, VOCAB);
    lp(k_logsoftmax, dim3(1), dim3(256), out);
}

// round 16
// speedup vs baseline: 1.0163x; 1.0163x over previous
#include <cuda_runtime.h>
#include <cuda_bf16.h>
#include <math.h>

#define L     8
#define NH    16
#define DH    64
#define SMAX  2048
#define H     1024
#define FFN   4096
#define ENC   1500
#define VOCAB 8192
#define FCH   48
#define CH    64    // attention key chunks
#define CSH   8.0f  // constant softmax shift (softmax is shift-invariant)

// ---------------- device state ----------------
__device__ __align__(16) float g_x[H];
__device__ __align__(16) float g_qkv[3 * H];
__device__ __align__(16) float g_qc[H];
__device__ __align__(16) float g_U[NH * H];
__device__ __align__(16) float g_sc[NH * ENC];
__device__ __align__(16) float g_W[NH * H];
__device__ __align__(16) float g_outc[H];
__device__ __align__(16) float g_ffn[FFN];
__device__ __align__(16) float g_logits[VOCAB];
__device__ float g_pm[NH * CH];
__device__ float g_ps[NH * CH];
__device__ __align__(16) float g_po[NH * CH * DH];
__device__ float g_ssum[NH];
__device__ int   g_step_fallback[1] = {512};

// ---------------- PDL helpers ----------------
__device__ __forceinline__ void pdl_trigger() {
#if defined(__CUDA_ARCH__) && __CUDA_ARCH__ >= 900
    cudaTriggerProgrammaticLaunchCompletion();
#endif
}
__device__ __forceinline__ void pdl_sync() {
#if defined(__CUDA_ARCH__) && __CUDA_ARCH__ >= 900
    cudaGridDependencySynchronize();
#endif
}

// ---------------- block reductions ----------------
__device__ __forceinline__ float br_sum(float v, float* sb) {
    int tid = threadIdx.x, lane = tid & 31, w = tid >> 5;
#pragma unroll
    for (int o = 16; o; o >>= 1) v += __shfl_down_sync(0xffffffffu, v, o);
    if (lane == 0) sb[w] = v;
    __syncthreads();
    if (tid < 32) {
        int nw = (blockDim.x + 31) >> 5;
        float x = (tid < nw) ? sb[tid] : 0.0f;
#pragma unroll
        for (int o = 16; o; o >>= 1) x += __shfl_down_sync(0xffffffffu, x, o);
        if (tid == 0) sb[0] = x;
    }
    __syncthreads();
    float r = sb[0];
    __syncthreads();
    return r;
}

__device__ __forceinline__ float br_max(float v, float* sb) {
    int tid = threadIdx.x, lane = tid & 31, w = tid >> 5;
#pragma unroll
    for (int o = 16; o; o >>= 1) v = fmaxf(v, __shfl_down_sync(0xffffffffu, v, o));
    if (lane == 0) sb[w] = v;
    __syncthreads();
    if (tid < 32) {
        int nw = (blockDim.x + 31) >> 5;
        float x = (tid < nw) ? sb[tid] : -1e30f;
#pragma unroll
        for (int o = 16; o; o >>= 1) x = fmaxf(x, __shfl_down_sync(0xffffffffu, x, o));
        if (tid == 0) sb[0] = x;
    }
    __syncthreads();
    float r = sb[0];
    __syncthreads();
    return r;
}

__device__ __forceinline__ void ln_stats(float* sb, float& mean, float& rstd) {
    int tid = threadIdx.x;
    float s = 0.f;
    for (int i = tid; i < H; i += blockDim.x) s += g_x[i];
    mean = br_sum(s, sb) * (1.0f / H);
    float v = 0.f;
    for (int i = tid; i < H; i += blockDim.x) { float d = g_x[i] - mean; v += d * d; }
    rstd = rsqrtf(br_sum(v, sb) * (1.0f / H) + 1e-5f);
}

// ---------------- kernels ----------------

// one-wave grid-stride cache copy (R14 config); nothing downstream syncs on it
__global__ void k_copy_p(const float4* __restrict__ ck, const float4* __restrict__ cv,
                         float4* __restrict__ nk, float4* __restrict__ nv,
                         const int* __restrict__ stepp) {
    pdl_trigger();
    int step = stepp[0];
    const size_t half = (size_t)L * NH * SMAX * 16;
    const size_t total = 2 * half;
    size_t stride = (size_t)gridDim.x * blockDim.x;
    for (size_t idx = (size_t)blockIdx.x * blockDim.x + threadIdx.x; idx < total; idx += stride) {
        const float4* src; float4* dst; size_t pos;
        if (idx < half) { src = ck; dst = nk; pos = idx; }
        else            { src = cv; dst = nv; pos = idx - half; }
        int t = (int)((pos >> 4) & (SMAX - 1));
        if (t < step)      dst[pos] = src[pos];
        else if (t > step) dst[pos] = make_float4(0.f, 0.f, 0.f, 0.f);
    }
}

// x = tok+pos; zero qkv + logits
__global__ void k_init(const int* __restrict__ idp, const int* __restrict__ stepp,
                       const float* __restrict__ tok, const float* __restrict__ pos) {
    pdl_trigger();
    int tid = threadIdx.x;  // 1024
    int id = idp[0], st = stepp[0];
    g_x[tid] = tok[(size_t)id * H + tid] + pos[(size_t)st * H + tid];
    for (int i = tid; i < 3 * H; i += 1024) g_qkv[i] = 0.f;
    for (int i = tid; i < VOCAB; i += 1024) g_logits[i] = 0.f;
}

// qkv += LN1(x) @ [Wq|Wk|Wv] (grid (6,32), 256); float2 prefetch, R=32
__global__ void k_gemv3_ln(const float* __restrict__ Wq, const float* __restrict__ Wk,
                           const float* __restrict__ Wv,
                           const float* __restrict__ g, const float* __restrict__ b) {
    __shared__ float sb[32];
    __shared__ float hc[32];
    int tid = threadIdx.x;
    pdl_trigger();
    int i0 = blockIdx.y * 32;
    int m = blockIdx.x >> 1;                       // matrix 0..2
    int j2 = (blockIdx.x & 1) * 512 + tid * 2;     // col pair in 0..1022
    const float* Wm = (m == 0) ? Wq : ((m == 1) ? Wk : Wv);
    float2 w[32];
#pragma unroll
    for (int r = 0; r < 32; r++) w[r] = *(const float2*)(Wm + (size_t)(i0 + r) * H + j2);
    pdl_sync();
    float mean, rstd;
    ln_stats(sb, mean, rstd);
    if (tid < 32) { int i = i0 + tid; hc[tid] = (g_x[i] - mean) * rstd * g[i] + b[i]; }
    __syncthreads();
    float2 acc = make_float2(0.f, 0.f);
#pragma unroll
    for (int r = 0; r < 32; r++) {
        float a = hc[r];
        acc.x += a * w[r].x; acc.y += a * w[r].y;
    }
    float* o = &g_qkv[m * H + j2];
    atomicAdd(o, acc.x); atomicAdd(o + 1, acc.y);
}

// out += LN(x; g,b) @ W  (grid: n_out/512 x K/32, block 256); float2, R=32
__global__ void k_gemv_ln(const float* __restrict__ Wm,
                          const float* __restrict__ g, const float* __restrict__ b,
                          float* __restrict__ out, int n_out) {
    __shared__ float sb[32];
    __shared__ float hc[32];
    int tid = threadIdx.x;
    pdl_trigger();
    int i0 = blockIdx.y * 32;
    int j2 = blockIdx.x * 512 + tid * 2;
    float2 w[32];
#pragma unroll
    for (int r = 0; r < 32; r++) w[r] = *(const float2*)(Wm + (size_t)(i0 + r) * n_out + j2);
    pdl_sync();
    float mean, rstd;
    ln_stats(sb, mean, rstd);
    if (tid < 32) { int i = i0 + tid; hc[tid] = (g_x[i] - mean) * rstd * g[i] + b[i]; }
    __syncthreads();
    float2 acc = make_float2(0.f, 0.f);
#pragma unroll
    for (int r = 0; r < 32; r++) {
        float a = hc[r];
        acc.x += a * w[r].x; acc.y += a * w[r].y;
    }
    float* o = &out[j2];
    atomicAdd(o, acc.x); atomicAdd(o + 1, acc.y);
}

// out += (relu?)a @ W; float2, SER serial 32-row chunks; optional zero buffer
template <int SER>
__global__ void k_gemv_plain(const float* __restrict__ Wm, const float* __restrict__ a,
                             float* __restrict__ out, int n_out, int relu,
                             float* z1, int zn1) {
    __shared__ float ac[32 * SER];
    int tid = threadIdx.x;
    pdl_trigger();
    int i0 = blockIdx.y * 32 * SER;
    int j2 = blockIdx.x * 512 + tid * 2;
    float2 w[32];
#pragma unroll
    for (int r = 0; r < 32; r++) w[r] = *(const float2*)(Wm + (size_t)(i0 + r) * n_out + j2);
    pdl_sync();
    if (zn1 > 0) {
        int gt = (blockIdx.y * gridDim.x + blockIdx.x) * 256 + tid;
        int T = gridDim.x * gridDim.y * 256;
        for (int k = gt; k < zn1; k += T) z1[k] = 0.f;
    }
    if (tid < 32 * SER) { float x = a[i0 + tid]; if (relu) x = fmaxf(x, 0.f); ac[tid] = x; }
    __syncthreads();
    float2 acc = make_float2(0.f, 0.f);
#pragma unroll
    for (int s = 0; s < SER; s++) {
#pragma unroll
        for (int r = 0; r < 32; r++) {
            float v = ac[s * 32 + r];
            acc.x += v * w[r].x; acc.y += v * w[r].y;
        }
        if (s + 1 < SER) {
#pragma unroll
            for (int r = 0; r < 32; r++)
                w[r] = *(const float2*)(Wm + (size_t)(i0 + (s + 1) * 32 + r) * n_out + j2);
        }
    }
    float* o = &out[j2];
    atomicAdd(o, acc.x); atomicAdd(o + 1, acc.y);
}

// x += merge(attn partials) @ Wo (grid (2,32), 256); zeros g_qc + g_ssum; float2
__global__ void k_gemv_merge(const float* __restrict__ Wm) {
    __shared__ float ac[32];
    int tid = threadIdx.x;
    pdl_trigger();
    int i0 = blockIdx.y * 32;
    int j2 = blockIdx.x * 512 + tid * 2;
    float2 w[32];
#pragma unroll
    for (int r = 0; r < 32; r++) w[r] = *(const float2*)(Wm + (size_t)(i0 + r) * H + j2);
    pdl_sync();
    int gt = (blockIdx.y * gridDim.x + blockIdx.x) * 256 + tid;
    int T = gridDim.x * gridDim.y * 256;
    for (int k = gt; k < H; k += T) g_qc[k] = 0.f;
    for (int k = gt; k < NH; k += T) g_ssum[k] = 0.f;
    if (tid < 32) {
        int i = i0 + tid;
        int h = i >> 6, d = i & 63;
        float M = -1e30f;
#pragma unroll
        for (int c = 0; c < CH; c++) M = fmaxf(M, g_pm[h * CH + c]);
        float S = 0.f, o = 0.f;
#pragma unroll
        for (int c = 0; c < CH; c++) {
            float e = __expf(g_pm[h * CH + c] - M);
            S += g_ps[h * CH + c] * e;
            o += e * g_po[(h * CH + c) * 64 + d];
        }
        ac[tid] = o / S;
    }
    __syncthreads();
    float2 acc = make_float2(0.f, 0.f);
#pragma unroll
    for (int r = 0; r < 32; r++) {
        float a = ac[r];
        acc.x += a * w[r].x; acc.y += a * w[r].y;
    }
    float* o = &g_x[j2];
    atomicAdd(o, acc.x); atomicAdd(o + 1, acc.y);
}

// flash-decode partials (grid (16,CH), block 128) [R12]
__global__ void k_attn_part(const float* __restrict__ ck, const float* __restrict__ cv,
                            float* __restrict__ nk, float* __restrict__ nv,
                            const int* __restrict__ stepp, int l) {
    __shared__ float2 q2[32];
    __shared__ float sc[72];
    __shared__ float sb[32];
    __shared__ float2 red2[128];
    int tid = threadIdx.x;
    pdl_trigger();
    pdl_sync();
    int h = blockIdx.x, c = blockIdx.y;
    int step = stepp[0];
    int n = step + 1;
    int cs = (n + CH - 1) / CH;
    int k0 = c * cs;
    int k1 = min(n, k0 + cs);
    int cnt = k1 - k0;
    int w = tid >> 5, lane = tid & 31;
    if (tid < 32) q2[tid] = ((const float2*)&g_qkv[h * 64])[tid];
    __syncthreads();
    float2 q = q2[lane];
    const float* kbase = ck + (size_t)(l * NH + h) * SMAX * DH;
    for (int kk = k0 + w; kk < k1; kk += 4) {
        const float2* kp = (kk < step) ? (const float2*)(kbase + (size_t)kk * DH)
                                       : (const float2*)(&g_qkv[H + h * 64]);
        float2 kv = kp[lane];
        float v = kv.x * q.x + kv.y * q.y;
#pragma unroll
        for (int o = 16; o; o >>= 1) v += __shfl_down_sync(0xffffffffu, v, o);
        if (lane == 0) sc[kk - k0] = v * 0.125f;
    }
    __syncthreads();
    float m = -1e30f;
    for (int i = tid; i < cnt; i += 128) m = fmaxf(m, sc[i]);
    m = br_max(m, sb);
    float s = 0.f;
    for (int i = tid; i < cnt; i += 128) { float e = __expf(sc[i] - m); sc[i] = e; s += e; }
    s = br_sum(s, sb);
    const float* vbase = cv + (size_t)(l * NH + h) * SMAX * DH;
    float2 acc = make_float2(0.f, 0.f);
    for (int kk = k0 + w; kk < k1; kk += 4) {
        const float2* vp = (kk < step) ? (const float2*)(vbase + (size_t)kk * DH)
                                       : (const float2*)(&g_qkv[2 * H + h * 64]);
        float wgt = sc[kk - k0];
        float2 v = vp[lane];
        acc.x += wgt * v.x; acc.y += wgt * v.y;
    }
    red2[tid] = acc;
    __syncthreads();
    if (w == 0) {
        float2 o;
        o.x = red2[lane].x + red2[32 + lane].x + red2[64 + lane].x + red2[96 + lane].x;
        o.y = red2[lane].y + red2[32 + lane].y + red2[64 + lane].y + red2[96 + lane].y;
        g_po[(h * CH + c) * 64 + 2 * lane]     = o.x;
        g_po[(h * CH + c) * 64 + 2 * lane + 1] = o.y;
        if (lane == 0) { g_pm[h * CH + c] = m; g_ps[h * CH + c] = s; }
    }
    if (c == 0 && tid >= 64) {
        int t2 = tid - 64;
        size_t base = ((size_t)(l * NH + h) * SMAX + step) * DH;
        if (t2 < 32) ((float2*)(nk + base))[t2]      = ((const float2*)(g_qkv + H + h * 64))[t2];
        else         ((float2*)(nv + base))[t2 - 32] = ((const float2*)(g_qkv + 2 * H + h * 64))[t2 - 32];
    }
}

// U[h][i]; zeros g_W and g_outc. grid 128, block 256 [R14]
__global__ void k_U(const float* __restrict__ Ck) {
    __shared__ float4 qs[256];
    int tid = threadIdx.x;
    pdl_trigger();
    pdl_sync();
    qs[tid] = ((const float4*)g_qc)[tid];
    int gt = blockIdx.x * 256 + tid;  // 0..32767
    if (gt < NH * H) g_W[gt] = 0.f;
    else if (gt < NH * H + H) g_outc[gt - NH * H] = 0.f;
    __syncthreads();
    float4 q = qs[tid];
    int i0 = blockIdx.x * 8;
    int h = tid >> 4;
#pragma unroll
    for (int r = 0; r < 8; r++) {
        int i = i0 + r;
        float4 w = ((const float4*)(Ck + (size_t)i * H))[tid];
        float v = w.x * q.x + w.y * q.y + w.z * q.z + w.w * q.w;
        v += __shfl_down_sync(0xffffffffu, v, 8);
        v += __shfl_down_sync(0xffffffffu, v, 4);
        v += __shfl_down_sync(0xffffffffu, v, 2);
        v += __shfl_down_sync(0xffffffffu, v, 1);
        if ((tid & 15) == 0) g_U[h * H + i] = v;
    }
}

// scores -> exp(s - CSH) written directly; per-head sums via one atomic per warp [R14]
__global__ void k_scores(const float* __restrict__ enc, const float* __restrict__ cmask) {
    pdl_trigger();
    pdl_sync();
    int w = threadIdx.x >> 5, lane = threadIdx.x & 31;
    const float4* up = (const float4*)(g_U + w * H);
    float4 u[8];
#pragma unroll
    for (int j = 0; j < 8; j++) u[j] = up[lane + 32 * j];
    float psum = 0.f;
#pragma unroll
    for (int ff = 0; ff < 8; ff++) {
        int f = blockIdx.x * 8 + ff;
        if (f >= ENC) break;
        const float4* ep = (const float4*)(enc + (size_t)f * H);
        float acc = 0.f;
#pragma unroll
        for (int j = 0; j < 8; j++) {
            float4 e = ep[lane + 32 * j];
            acc += e.x * u[j].x + e.y * u[j].y + e.z * u[j].z + e.w * u[j].w;
        }
#pragma unroll
        for (int o = 16; o; o >>= 1) acc += __shfl_down_sync(0xffffffffu, acc, o);
        if (lane == 0) {
            float e = __expf(acc * 0.125f + cmask[f] - CSH);
            g_sc[w * ENC + f] = e;
            psum += e;
        }
    }
    if (lane == 0) atomicAdd(&g_ssum[w], psum);
}

// W[h][cols] += (exp-scores / ssum[h]) @ enc. grid (4,32), block 256 [R14]
__global__ void k_wsum(const float* __restrict__ enc) {
    __shared__ float at[4 * FCH];
    __shared__ float rs[4];
    int tid = threadIdx.x, fc = blockIdx.y, hg = blockIdx.x;
    pdl_trigger();
    pdl_sync();
    if (tid < 4) rs[tid] = 1.0f / g_ssum[hg * 4 + tid];
    __syncthreads();
    for (int idx = tid; idx < 4 * FCH; idx += 256) {
        int hh = idx / FCH, k = idx % FCH;
        int f = fc * FCH + k;
        at[idx] = (f < ENC) ? g_sc[(hg * 4 + hh) * ENC + f] * rs[hh] : 0.f;
    }
    __syncthreads();
    int c0 = tid * 4;
    float4 acc[4];
#pragma unroll
    for (int hh = 0; hh < 4; hh++) acc[hh] = make_float4(0.f, 0.f, 0.f, 0.f);
    int fend = min(FCH, ENC - fc * FCH);
    for (int k = 0; k < fend; k++) {
        float4 e = *(const float4*)(enc + (size_t)(fc * FCH + k) * H + c0);
#pragma unroll
        for (int hh = 0; hh < 4; hh++) {
            float a = at[hh * FCH + k];
            acc[hh].x += a * e.x; acc[hh].y += a * e.y;
            acc[hh].z += a * e.z; acc[hh].w += a * e.w;
        }
    }
#pragma unroll
    for (int hh = 0; hh < 4; hh++) {
        float* o = &g_W[(hg * 4 + hh) * H + c0];
        atomicAdd(o, acc[hh].x); atomicAdd(o + 1, acc[hh].y);
        atomicAdd(o + 2, acc[hh].z); atomicAdd(o + 3, acc[hh].w);
    }
}

// outc[col] += sum_i W[h(col),i]*Cv[i,col]; zero g_ffn. grid 128, block 256 [R12]
__global__ void k_outc(const float* __restrict__ Cv) {
    int tid = threadIdx.x;
    pdl_trigger();
    pdl_sync();
    int c0 = tid * 4;
    int h = tid >> 4;
    int i0 = blockIdx.x * 8;
    float4 acc = make_float4(0.f, 0.f, 0.f, 0.f);
#pragma unroll
    for (int r = 0; r < 8; r++) {
        int i = i0 + r;
        float wv = g_W[h * H + i];
        float4 cv4 = *(const float4*)(Cv + (size_t)i * H + c0);
        acc.x += wv * cv4.x; acc.y += wv * cv4.y;
        acc.z += wv * cv4.z; acc.w += wv * cv4.w;
    }
    float* o = &g_outc[c0];
    atomicAdd(o, acc.x); atomicAdd(o + 1, acc.y);
    atomicAdd(o + 2, acc.z); atomicAdd(o + 3, acc.w);
    int gt = blockIdx.x * 256 + tid;
    if (gt < FFN) g_ffn[gt] = 0.f;
}

__global__ void k_logsoftmax(float* __restrict__ out) {
    __shared__ float sb[32];
    int tid = threadIdx.x;
    pdl_trigger();
    pdl_sync();
    float m = -1e30f;
    for (int i = tid; i < VOCAB; i += 256) m = fmaxf(m, g_logits[i]);
    m = br_max(m, sb);
    float s = 0.f;
    for (int i = tid; i < VOCAB; i += 256) s += __expf(g_logits[i] - m);
    s = br_sum(s, sb);
    float ls = logf(s);
    for (int i = tid; i < VOCAB; i += 256) out[i] = g_logits[i] - m - ls;
}

// ---------------- host ----------------
template <typename... Args>
static inline void lp(void (*k)(Args...), dim3 g, dim3 b, Args... a) {
    cudaLaunchConfig_t cfg = {};
    cfg.gridDim = g; cfg.blockDim = b;
    cfg.dynamicSmemBytes = 0; cfg.stream = 0;
    cudaLaunchAttribute at[1];
    at[0].id = cudaLaunchAttributeProgrammaticStreamSerialization;
    at[0].val.programmaticStreamSerializationAllowed = 1;
    cfg.attrs = at; cfg.numAttrs = 1;
    cudaLaunchKernelEx(&cfg, k, a...);
}

extern "C" void kernel_launch(void* const* d_in, const int* in_sizes, int n_in,
                              void* d_out, int out_size) {
    int has_step = (n_in >= 27) ? 1 : 0;
    int idx = 0;
    const int*   input_id = (const int*)d_in[idx++];
    const float* enc      = (const float*)d_in[idx++];
    const float* ck       = (const float*)d_in[idx++];
    const float* cv       = (const float*)d_in[idx++];
    const int*   stepp    = nullptr;
    if (has_step) stepp = (const int*)d_in[idx++];
    const float* cmask = (const float*)d_in[idx++];
    const float* tok   = (const float*)d_in[idx++];
    const float* pos   = (const float*)d_in[idx++];
    const float* Wq = (const float*)d_in[idx++];
    const float* Wk = (const float*)d_in[idx++];
    const float* Wv = (const float*)d_in[idx++];
    const float* Wo = (const float*)d_in[idx++];
    const float* Cq = (const float*)d_in[idx++];
    const float* Ck = (const float*)d_in[idx++];
    const float* Cv = (const float*)d_in[idx++];
    const float* Co = (const float*)d_in[idx++];
    const float* W1 = (const float*)d_in[idx++];
    const float* W2 = (const float*)d_in[idx++];
    const float* ln1g = (const float*)d_in[idx++];
    const float* ln1b = (const float*)d_in[idx++];
    const float* ln2g = (const float*)d_in[idx++];
    const float* ln2b = (const float*)d_in[idx++];
    const float* ln3g = (const float*)d_in[idx++];
    const float* ln3b = (const float*)d_in[idx++];
    const float* lnfg = (const float*)d_in[idx++];
    const float* lnfb = (const float*)d_in[idx++];
    const float* Wout = (const float*)d_in[idx++];

    if (!stepp) {
        void* p;
        cudaGetSymbolAddress(&p, g_step_fallback);
        stepp = (const int*)p;
    }

    float* out = (float*)d_out;
    float* nk = out + VOCAB;
    float* nv = nk + (size_t)L * NH * SMAX * DH;

    float *p_qc, *p_outc, *p_ffn, *p_logits, *p_qkv, *p_x;
    cudaGetSymbolAddress((void**)&p_x, g_x);
    cudaGetSymbolAddress((void**)&p_qc, g_qc);
    cudaGetSymbolAddress((void**)&p_outc, g_outc);
    cudaGetSymbolAddress((void**)&p_ffn, g_ffn);
    cudaGetSymbolAddress((void**)&p_logits, g_logits);
    cudaGetSymbolAddress((void**)&p_qkv, g_qkv);

    // cache copy: one wave (R14 config); free-running overlap
    lp(k_copy_p, dim3(296), dim3(1024),
       (const float4*)ck, (const float4*)cv, (float4*)nk, (float4*)nv, stepp);
    lp(k_init, dim3(1), dim3(1024), input_id, stepp, tok, pos);

    for (int l = 0; l < L; l++) {
        size_t o = (size_t)l * H * H;
        size_t o1 = (size_t)l * H * FFN;
        size_t o2 = (size_t)l * FFN * H;
        // self-attention (float2 GEMVs, R=32)
        lp(k_gemv3_ln, dim3(6, 32), dim3(256), Wq + o, Wk + o, Wv + o,
           (const float*)(ln1g + l * H), (const float*)(ln1b + l * H));
        lp(k_attn_part, dim3(16, CH), dim3(128), ck, cv, nk, nv, stepp, l);
        lp(k_gemv_merge, dim3(2, 32), dim3(256), Wo + o);
        // cross-attention
        lp(k_gemv_ln, dim3(2, 32), dim3(256), Cq + o,
           (const float*)(ln2g + l * H), (const float*)(ln2b + l * H), p_qc, H);
        lp(k_U, dim3(128), dim3(256), Ck + o);
        lp(k_scores, dim3(188), dim3(512), enc, cmask);
        lp(k_wsum, dim3(4, 32), dim3(256), enc);
        lp(k_outc, dim3(128), dim3(256), Cv + o);
        lp(k_gemv_plain<1>, dim3(2, 32), dim3(256), Co + o, (const float*)p_outc, p_x, H, 0,
           (float*)nullptr, 0);
        // FFN
        lp(k_gemv_ln, dim3(8, 32), dim3(256), W1 + o1,
           (const float*)(ln3g + l * H), (const float*)(ln3b + l * H), p_ffn, FFN);
        lp(k_gemv_plain<2>, dim3(2, 64), dim3(256), W2 + o2, (const float*)p_ffn, p_x, H, 1,
           p_qkv, 3 * H);
    }
    // final projection + log-softmax
    lp(k_gemv_ln, dim3(16, 32), dim3(256), Wout, lnfg, lnfb, p_logits, VOCAB);
    lp(k_logsoftmax, dim3(1), dim3(256), out);
}